// round 4
// baseline (speedup 1.0000x reference)
#include <cuda_runtime.h>
#include <math.h>

#define N_TOK 4096      // B*S
#define DDIM  1024      // D
#define FDIM  4096      // F
#define NEXP  8         // E
#define LN_EPS 1e-5f

#define BM 128
#define BN 128
#define BK 16

// ---- static device scratch (no runtime allocation allowed) ----
__device__ int   g_counts[NEXP];
__device__ int   g_rows[NEXP * N_TOK];          // value = token*2 + slot
__device__ float g_slotw[2 * N_TOK];            // softmax weight per slot
__device__ float g_H[(size_t)2 * N_TOK * FDIM]; // [8192][4096] relu(x@W1^T+b1)
__device__ float g_Y[(size_t)2 * N_TOK * DDIM]; // [8192][1024] H@W2^T+b2 (unweighted)

// ---------------------------------------------------------------
__global__ void init_counts_kernel() {
    if (threadIdx.x < NEXP) g_counts[threadIdx.x] = 0;
}

// One warp per token: 8 logits, top-2, softmax, append to expert lists.
__global__ void router_kernel(const float* __restrict__ tgt,
                              const float* __restrict__ Wr,
                              const float* __restrict__ br) {
    int token = blockIdx.x * 8 + (threadIdx.x >> 5);
    int lane  = threadIdx.x & 31;
    if (token >= N_TOK) return;

    const float* x = tgt + (size_t)token * DDIM;
    float xr[32];
#pragma unroll
    for (int i = 0; i < 32; i++) xr[i] = x[lane + 32 * i];

    float logits[NEXP];
#pragma unroll
    for (int e = 0; e < NEXP; e++) {
        const float* w = Wr + e * DDIM;
        float s = 0.f;
#pragma unroll
        for (int i = 0; i < 32; i++) s += xr[i] * w[lane + 32 * i];
#pragma unroll
        for (int o = 16; o > 0; o >>= 1) s += __shfl_xor_sync(0xffffffffu, s, o);
        logits[e] = s + br[e];
    }

    if (lane == 0) {
        // top-1 (lowest index wins ties, matching jax.lax.top_k)
        int i0 = 0; float v0 = logits[0];
#pragma unroll
        for (int e = 1; e < NEXP; e++) if (logits[e] > v0) { v0 = logits[e]; i0 = e; }
        int i1 = -1; float v1 = -INFINITY;
#pragma unroll
        for (int e = 0; e < NEXP; e++) if (e != i0 && logits[e] > v1) { v1 = logits[e]; i1 = e; }
        // softmax over [v0, v1] with v0 >= v1
        float e1  = expf(v1 - v0);
        float inv = 1.f / (1.f + e1);
        g_slotw[2 * token]     = inv;
        g_slotw[2 * token + 1] = e1 * inv;
        int p0 = atomicAdd(&g_counts[i0], 1); g_rows[i0 * N_TOK + p0] = 2 * token;
        int p1 = atomicAdd(&g_counts[i1], 1); g_rows[i1 * N_TOK + p1] = 2 * token + 1;
    }
}

// Grouped GEMM over per-expert row lists.
//   is_gemm1=1: A = tgt (row = rows[m]>>1, lda=D), B = W1[e] (FxD), out = g_H (row = rows[m], ldo=F), relu+b1
//   is_gemm1=0: A = g_H (row = rows[m],    lda=F), B = W2[e] (DxF), out = g_Y (row = rows[m], ldo=D), +b2
// C[m][n] = sum_k A[m][k] * B[n][k]  (both K-major -> A @ B^T)
__global__ __launch_bounds__(256, 2)
void expert_gemm_kernel(const float* __restrict__ tgt,
                        int is_gemm1,
                        const float* __restrict__ W,
                        int Ndim, int Kdim,
                        const float* __restrict__ bias) {
    __shared__ __align__(16) float As[BK][BM + 4];
    __shared__ __align__(16) float Bs[BK][BN + 4];

    int e  = blockIdx.z;
    int mt = blockIdx.y;
    int nt = blockIdx.x;
    int cnt = g_counts[e];
    if (mt * BM >= cnt) return;

    const int* erows = g_rows + e * N_TOK;
    const float* Abase = is_gemm1 ? tgt : g_H;
    float*       Outp  = is_gemm1 ? g_H : g_Y;
    int lda = is_gemm1 ? DDIM : FDIM;
    int ldo = is_gemm1 ? FDIM : DDIM;
    int row_shift = is_gemm1 ? 1 : 0;
    const float* Wb = W + (size_t)e * Ndim * Kdim;

    int tid = threadIdx.x;
    int tx = tid & 15, ty = tid >> 4;
    int lr = tid >> 2;          // load row within half-tile (0..63)
    int kc = (tid & 3) * 4;     // k offset of this thread's float4

    int gr0 = mt * BM + lr;      if (gr0 > cnt - 1) gr0 = cnt - 1;
    int gr1 = mt * BM + lr + 64; if (gr1 > cnt - 1) gr1 = cnt - 1;
    const float* a0 = Abase + (size_t)(erows[gr0] >> row_shift) * lda + kc;
    const float* a1 = Abase + (size_t)(erows[gr1] >> row_shift) * lda + kc;
    const float* b0 = Wb + (size_t)(nt * BN + lr) * Kdim + kc;
    const float* b1p = b0 + (size_t)64 * Kdim;

    float acc[8][8];
#pragma unroll
    for (int i = 0; i < 8; i++)
#pragma unroll
        for (int j = 0; j < 8; j++) acc[i][j] = 0.f;

    for (int k0 = 0; k0 < Kdim; k0 += BK) {
        float4 av0 = *(const float4*)a0;
        float4 av1 = *(const float4*)a1;
        float4 bv0 = *(const float4*)b0;
        float4 bv1 = *(const float4*)b1p;
        a0 += BK; a1 += BK; b0 += BK; b1p += BK;

        As[kc + 0][lr] = av0.x; As[kc + 1][lr] = av0.y; As[kc + 2][lr] = av0.z; As[kc + 3][lr] = av0.w;
        As[kc + 0][lr + 64] = av1.x; As[kc + 1][lr + 64] = av1.y; As[kc + 2][lr + 64] = av1.z; As[kc + 3][lr + 64] = av1.w;
        Bs[kc + 0][lr] = bv0.x; Bs[kc + 1][lr] = bv0.y; Bs[kc + 2][lr] = bv0.z; Bs[kc + 3][lr] = bv0.w;
        Bs[kc + 0][lr + 64] = bv1.x; Bs[kc + 1][lr + 64] = bv1.y; Bs[kc + 2][lr + 64] = bv1.z; Bs[kc + 3][lr + 64] = bv1.w;
        __syncthreads();

#pragma unroll
        for (int k = 0; k < BK; k++) {
            float ar[8], brg[8];
            *(float4*)(ar)     = *(const float4*)&As[k][ty * 8];
            *(float4*)(ar + 4) = *(const float4*)&As[k][ty * 8 + 4];
            *(float4*)(brg)     = *(const float4*)&Bs[k][tx * 8];
            *(float4*)(brg + 4) = *(const float4*)&Bs[k][tx * 8 + 4];
#pragma unroll
            for (int i = 0; i < 8; i++)
#pragma unroll
                for (int j = 0; j < 8; j++)
                    acc[i][j] += ar[i] * brg[j];
        }
        __syncthreads();
    }

    float bv[8];
#pragma unroll
    for (int j = 0; j < 8; j++) bv[j] = bias[e * Ndim + nt * BN + tx * 8 + j];

#pragma unroll
    for (int i = 0; i < 8; i++) {
        int mr = mt * BM + ty * 8 + i;
        if (mr < cnt) {
            int orow = erows[mr];
            float* op = Outp + (size_t)orow * ldo + nt * BN + tx * 8;
            float t[8];
#pragma unroll
            for (int j = 0; j < 8; j++) {
                float v = acc[i][j] + bv[j];
                if (is_gemm1) v = fmaxf(v, 0.f);
                t[j] = v;
            }
            *(float4*)op       = make_float4(t[0], t[1], t[2], t[3]);
            *(float4*)(op + 4) = make_float4(t[4], t[5], t[6], t[7]);
        }
    }
}

// residual + weighted combine + post-LayerNorm. One block (256 thr) per token.
__global__ void ln_kernel(const float* __restrict__ tgt,
                          const float* __restrict__ gamma,
                          const float* __restrict__ beta,
                          float* __restrict__ out) {
    int token = blockIdx.x;
    int tid = threadIdx.x;
    __shared__ float red[8];

    float w0 = g_slotw[2 * token], w1 = g_slotw[2 * token + 1];
    const float* x  = tgt + (size_t)token * DDIM;
    const float* y0 = g_Y + (size_t)(2 * token) * DDIM;
    const float* y1 = y0 + DDIM;

    float v[4];
    float s = 0.f;
#pragma unroll
    for (int i = 0; i < 4; i++) {
        int d = tid + 256 * i;
        v[i] = x[d] + w0 * y0[d] + w1 * y1[d];
        s += v[i];
    }
#pragma unroll
    for (int o = 16; o > 0; o >>= 1) s += __shfl_xor_sync(0xffffffffu, s, o);
    if ((tid & 31) == 0) red[tid >> 5] = s;
    __syncthreads();
    float mu = (red[0] + red[1] + red[2] + red[3] + red[4] + red[5] + red[6] + red[7]) * (1.f / DDIM);

    float sq = 0.f;
#pragma unroll
    for (int i = 0; i < 4; i++) { float dv = v[i] - mu; sq += dv * dv; }
#pragma unroll
    for (int o = 16; o > 0; o >>= 1) sq += __shfl_xor_sync(0xffffffffu, sq, o);
    __syncthreads();
    if ((tid & 31) == 0) red[tid >> 5] = sq;
    __syncthreads();
    float var = (red[0] + red[1] + red[2] + red[3] + red[4] + red[5] + red[6] + red[7]) * (1.f / DDIM);
    float inv = rsqrtf(var + LN_EPS);

#pragma unroll
    for (int i = 0; i < 4; i++) {
        int d = tid + 256 * i;
        out[(size_t)token * DDIM + d] = (v[i] - mu) * inv * gamma[d] + beta[d];
    }
}

// ---------------------------------------------------------------
extern "C" void kernel_launch(void* const* d_in, const int* in_sizes, int n_in,
                              void* d_out, int out_size) {
    const float* tgt   = (const float*)d_in[0];
    const float* Wr    = (const float*)d_in[1];
    const float* br    = (const float*)d_in[2];
    const float* W1    = (const float*)d_in[3];
    const float* b1    = (const float*)d_in[4];
    const float* W2    = (const float*)d_in[5];
    const float* b2    = (const float*)d_in[6];
    const float* gamma = (const float*)d_in[7];
    const float* beta  = (const float*)d_in[8];
    float* out = (float*)d_out;

    init_counts_kernel<<<1, 32>>>();
    router_kernel<<<N_TOK / 8, 256>>>(tgt, Wr, br);

    // GEMM1: [cnt_e, 1024] x [4096, 1024]^T -> H, relu
    dim3 g1(FDIM / BN, N_TOK / BM, NEXP);   // (32, 32, 8), early-exit on cnt
    expert_gemm_kernel<<<g1, 256>>>(tgt, 1, W1, FDIM, DDIM, b1);

    // GEMM2: [cnt_e, 4096] x [1024, 4096]^T -> Y
    dim3 g2(DDIM / BN, N_TOK / BM, NEXP);   // (8, 32, 8)
    expert_gemm_kernel<<<g2, 256>>>(tgt, 0, W2, DDIM, FDIM, b2);

    ln_kernel<<<N_TOK, 256>>>(tgt, gamma, beta, out);
}

// round 7
// speedup vs baseline: 1.8494x; 1.8494x over previous
#include <cuda_runtime.h>
#include <cuda_bf16.h>
#include <math.h>
#include <stdint.h>

#define N_TOK 4096      // B*S
#define DDIM  1024      // D
#define FDIM  4096      // F
#define NEXP  8         // E
#define LN_EPS 1e-5f

#define BM 128
#define BN 128
#define BK 32
#define ROWB 80                 // smem bytes per row: 32 bf16 + 8 pad = 80B
#define AT   (128 * ROWB)       // 10240 B per operand tile
#define BUFSZ (4 * AT)          // Ah, Al, Bh, Bl
#define SMEM_BYTES (2 * BUFSZ)  // 81920 B, double buffered

// ---- static device scratch (no runtime allocation allowed) ----
__device__ int   g_counts[NEXP];
__device__ int   g_rows[NEXP * N_TOK];          // value = token*2 + slot
__device__ float g_slotw[2 * N_TOK];            // softmax weight per slot
__device__ __nv_bfloat16 g_Xhi[N_TOK * DDIM];
__device__ __nv_bfloat16 g_Xlo[N_TOK * DDIM];
__device__ __nv_bfloat16 g_W1hi[NEXP * FDIM * DDIM];
__device__ __nv_bfloat16 g_W1lo[NEXP * FDIM * DDIM];
__device__ __nv_bfloat16 g_W2hi[NEXP * DDIM * FDIM];
__device__ __nv_bfloat16 g_W2lo[NEXP * DDIM * FDIM];
__device__ __nv_bfloat16 g_Hhi[(size_t)2 * N_TOK * FDIM];
__device__ __nv_bfloat16 g_Hlo[(size_t)2 * N_TOK * FDIM];
__device__ float g_Y[(size_t)2 * N_TOK * DDIM]; // [8192][1024] H@W2^T+b2 (unweighted)

// ============================ PTX helpers ============================
static __device__ __forceinline__ void cp16(uint32_t s, const void* g) {
    asm volatile("cp.async.cg.shared.global [%0], [%1], 16;" :: "r"(s), "l"(g));
}

#define LDSM4(r0, r1, r2, r3, addr)                                           \
    asm volatile("ldmatrix.sync.aligned.m8n8.x4.shared.b16 {%0,%1,%2,%3}, [%4];" \
                 : "=r"(r0), "=r"(r1), "=r"(r2), "=r"(r3) : "r"(addr))

#define MMA16816(d, a, b0, b1)                                                \
    asm volatile("mma.sync.aligned.m16n8k16.row.col.f32.bf16.bf16.f32 "       \
                 "{%0,%1,%2,%3}, {%4,%5,%6,%7}, {%8,%9}, {%0,%1,%2,%3};"      \
                 : "+f"((d)[0]), "+f"((d)[1]), "+f"((d)[2]), "+f"((d)[3])     \
                 : "r"((a)[0]), "r"((a)[1]), "r"((a)[2]), "r"((a)[3]),        \
                   "r"(b0), "r"(b1))

// ============================ small kernels ============================
__global__ void init_counts_kernel() {
    if (threadIdx.x < NEXP) g_counts[threadIdx.x] = 0;
}

// fp32 -> bf16 hi/lo split
__global__ void split_bf16_kernel(const float* __restrict__ src,
                                  __nv_bfloat16* __restrict__ hi,
                                  __nv_bfloat16* __restrict__ lo, int n) {
    int i = (blockIdx.x * blockDim.x + threadIdx.x) * 4;
    if (i >= n) return;
    float4 v = *(const float4*)(src + i);
    float vv[4] = {v.x, v.y, v.z, v.w};
    __nv_bfloat16 h[4], l[4];
#pragma unroll
    for (int j = 0; j < 4; j++) {
        h[j] = __float2bfloat16(vv[j]);
        l[j] = __float2bfloat16(vv[j] - __bfloat162float(h[j]));
    }
    __nv_bfloat162 h0; h0.x = h[0]; h0.y = h[1];
    __nv_bfloat162 h1; h1.x = h[2]; h1.y = h[3];
    __nv_bfloat162 l0; l0.x = l[0]; l0.y = l[1];
    __nv_bfloat162 l1; l1.x = l[2]; l1.y = l[3];
    *(__nv_bfloat162*)(hi + i)     = h0;
    *(__nv_bfloat162*)(hi + i + 2) = h1;
    *(__nv_bfloat162*)(lo + i)     = l0;
    *(__nv_bfloat162*)(lo + i + 2) = l1;
}

// One warp per token: 8 logits, top-2, softmax, append to expert lists.
__global__ void router_kernel(const float* __restrict__ tgt,
                              const float* __restrict__ Wr,
                              const float* __restrict__ br) {
    int token = blockIdx.x * 8 + (threadIdx.x >> 5);
    int lane  = threadIdx.x & 31;
    if (token >= N_TOK) return;

    const float* x = tgt + (size_t)token * DDIM;
    float xr[32];
#pragma unroll
    for (int i = 0; i < 32; i++) xr[i] = x[lane + 32 * i];

    float logits[NEXP];
#pragma unroll
    for (int e = 0; e < NEXP; e++) {
        const float* w = Wr + e * DDIM;
        float s = 0.f;
#pragma unroll
        for (int i = 0; i < 32; i++) s += xr[i] * w[lane + 32 * i];
#pragma unroll
        for (int o = 16; o > 0; o >>= 1) s += __shfl_xor_sync(0xffffffffu, s, o);
        logits[e] = s + br[e];
    }

    if (lane == 0) {
        int i0 = 0; float v0 = logits[0];
#pragma unroll
        for (int e = 1; e < NEXP; e++) if (logits[e] > v0) { v0 = logits[e]; i0 = e; }
        int i1 = -1; float v1 = -INFINITY;
#pragma unroll
        for (int e = 0; e < NEXP; e++) if (e != i0 && logits[e] > v1) { v1 = logits[e]; i1 = e; }
        float e1  = expf(v1 - v0);
        float inv = 1.f / (1.f + e1);
        g_slotw[2 * token]     = inv;
        g_slotw[2 * token + 1] = e1 * inv;
        int p0 = atomicAdd(&g_counts[i0], 1); g_rows[i0 * N_TOK + p0] = 2 * token;
        int p1 = atomicAdd(&g_counts[i1], 1); g_rows[i1 * N_TOK + p1] = 2 * token + 1;
    }
}

// ============================ mma.sync grouped GEMM ============================
// C[m][n] = sum_k A[m][k]*B[n][k], A/B each split bf16 hi+lo:
//   D += Ah*Bh + Ah*Bl + Al*Bh  (fp32 register accumulate)
// 256 thr = 8 warps (2 M x 4 N), warp tile 64x32, block tile 128x128, BK=32.
__global__ void __launch_bounds__(256, 2)
mma_gemm_kernel(int is_gemm1, int Ndim, int Kdim, const float* __restrict__ bias) {
    extern __shared__ __align__(128) char smem[];
    uint32_t sb = (uint32_t)__cvta_generic_to_shared(smem);

    int e  = blockIdx.z;
    int nt = blockIdx.y;
    int mt = blockIdx.x;     // mt varies fastest -> consecutive blocks share weight tile (L2)
    int cnt = g_counts[e];
    if (mt * BM >= cnt) return;

    const int* erows = g_rows + e * N_TOK;
    const __nv_bfloat16 *Ahb, *Alb, *Whb, *Wlb;
    if (is_gemm1) { Ahb = g_Xhi; Alb = g_Xlo; Whb = g_W1hi; Wlb = g_W1lo; }
    else          { Ahb = g_Hhi; Alb = g_Hlo; Whb = g_W2hi; Wlb = g_W2lo; }

    int tid = threadIdx.x;

    // ---- global->smem load geometry: thread -> (row = tid>>1, 32B half = tid&1) ----
    int lrow = tid >> 1;
    int kb = (tid & 1) * 16;                 // element offset of this thread's 32B
    int mr_l = mt * BM + lrow; if (mr_l > cnt - 1) mr_l = cnt - 1;
    int arow = erows[mr_l]; if (is_gemm1) arow >>= 1;
    const __nv_bfloat16* aph = Ahb + (size_t)arow * Kdim + kb;
    const __nv_bfloat16* apl = Alb + (size_t)arow * Kdim + kb;
    size_t wo = ((size_t)e * Ndim + nt * BN + lrow) * Kdim + kb;
    const __nv_bfloat16* bph = Whb + wo;
    const __nv_bfloat16* bpl = Wlb + wo;
    uint32_t dst = (uint32_t)lrow * ROWB + (tid & 1) * 32;

    // ---- fragment (ldmatrix) geometry ----
    int lane = tid & 31, wid = tid >> 5;
    int wm = wid & 1, wn = wid >> 1;         // warp tile origin (wm*64, wn*32)
    uint32_t afa = (uint32_t)(wm * 64 + (lane & 15)) * ROWB + (lane >> 4) * 16;
    uint32_t bfa = (uint32_t)(wn * 32 + (lane & 15)) * ROWB + (lane >> 4) * 16;

    float acc[4][4][4];
#pragma unroll
    for (int mi = 0; mi < 4; mi++)
#pragma unroll
        for (int ni = 0; ni < 4; ni++)
#pragma unroll
            for (int r = 0; r < 4; r++) acc[mi][ni][r] = 0.f;

    auto issue = [&](int i, int b) {
        uint32_t d = sb + (uint32_t)b * BUFSZ + dst;
        size_t ko = (size_t)i * BK;
        cp16(d,               aph + ko); cp16(d + 16,          aph + ko + 8);
        cp16(d + AT,          apl + ko); cp16(d + AT + 16,     apl + ko + 8);
        cp16(d + 2 * AT,      bph + ko); cp16(d + 2 * AT + 16, bph + ko + 8);
        cp16(d + 3 * AT,      bpl + ko); cp16(d + 3 * AT + 16, bpl + ko + 8);
        asm volatile("cp.async.commit_group;" ::: "memory");
    };

    int nch = Kdim / BK;
    issue(0, 0);
    for (int i = 0; i < nch; i++) {
        if (i + 1 < nch) {
            issue(i + 1, (i + 1) & 1);
            asm volatile("cp.async.wait_group 1;" ::: "memory");
        } else {
            asm volatile("cp.async.wait_group 0;" ::: "memory");
        }
        __syncthreads();

        uint32_t bb = sb + (uint32_t)(i & 1) * BUFSZ;
#pragma unroll
        for (int s = 0; s < 2; s++) {       // two k16 steps per chunk
#pragma unroll
            for (int p = 0; p < 3; p++) {   // (Ah,Bh), (Ah,Bl), (Al,Bh)
                uint32_t ab  = bb + ((p == 2) ? AT : 0u) + afa + s * 32;
                uint32_t bbp = bb + 2 * AT + ((p == 1) ? AT : 0u) + bfa + s * 32;
                uint32_t a[4][4], bq[2][4];
#pragma unroll
                for (int mi = 0; mi < 4; mi++)
                    LDSM4(a[mi][0], a[mi][1], a[mi][2], a[mi][3], ab + mi * 16 * ROWB);
#pragma unroll
                for (int nj = 0; nj < 2; nj++)
                    LDSM4(bq[nj][0], bq[nj][1], bq[nj][2], bq[nj][3], bbp + nj * 16 * ROWB);
#pragma unroll
                for (int mi = 0; mi < 4; mi++)
#pragma unroll
                    for (int ni = 0; ni < 4; ni++)
                        MMA16816(acc[mi][ni], a[mi],
                                 bq[ni >> 1][ni & 1], bq[ni >> 1][(ni & 1) + 2]);
            }
        }
        __syncthreads();
    }

    // ---- epilogue ----
    int tg = lane >> 2, tc = (lane & 3) * 2;
    const float* bbias = bias + e * Ndim + nt * BN;
#pragma unroll
    for (int mi = 0; mi < 4; mi++) {
#pragma unroll
        for (int half = 0; half < 2; half++) {
            int r = wm * 64 + mi * 16 + tg + half * 8;
            int mr = mt * BM + r;
            if (mr < cnt) {
                int orow = erows[mr];
#pragma unroll
                for (int ni = 0; ni < 4; ni++) {
                    int c = wn * 32 + ni * 8 + tc;
                    float v0 = acc[mi][ni][half * 2]     + __ldg(bbias + c);
                    float v1 = acc[mi][ni][half * 2 + 1] + __ldg(bbias + c + 1);
                    int n = nt * BN + c;
                    if (is_gemm1) {
                        v0 = fmaxf(v0, 0.f); v1 = fmaxf(v1, 0.f);
                        __nv_bfloat16 h0 = __float2bfloat16(v0);
                        __nv_bfloat16 h1 = __float2bfloat16(v1);
                        __nv_bfloat162 hh; hh.x = h0; hh.y = h1;
                        __nv_bfloat162 ll;
                        ll.x = __float2bfloat16(v0 - __bfloat162float(h0));
                        ll.y = __float2bfloat16(v1 - __bfloat162float(h1));
                        *(__nv_bfloat162*)(g_Hhi + (size_t)orow * FDIM + n) = hh;
                        *(__nv_bfloat162*)(g_Hlo + (size_t)orow * FDIM + n) = ll;
                    } else {
                        float2 t; t.x = v0; t.y = v1;
                        *(float2*)(g_Y + (size_t)orow * DDIM + n) = t;
                    }
                }
            }
        }
    }
}

// ============================ LN ============================
__global__ void ln_kernel(const float* __restrict__ tgt,
                          const float* __restrict__ gamma,
                          const float* __restrict__ beta,
                          float* __restrict__ out) {
    int token = blockIdx.x;
    int tid = threadIdx.x;
    __shared__ float red[8];

    float w0 = g_slotw[2 * token], w1 = g_slotw[2 * token + 1];
    const float* x  = tgt + (size_t)token * DDIM;
    const float* y0 = g_Y + (size_t)(2 * token) * DDIM;
    const float* y1 = y0 + DDIM;

    float v[4];
    float s = 0.f;
#pragma unroll
    for (int i = 0; i < 4; i++) {
        int d = tid + 256 * i;
        v[i] = x[d] + w0 * y0[d] + w1 * y1[d];
        s += v[i];
    }
#pragma unroll
    for (int o = 16; o > 0; o >>= 1) s += __shfl_xor_sync(0xffffffffu, s, o);
    if ((tid & 31) == 0) red[tid >> 5] = s;
    __syncthreads();
    float mu = (red[0] + red[1] + red[2] + red[3] + red[4] + red[5] + red[6] + red[7]) * (1.f / DDIM);

    float sq = 0.f;
#pragma unroll
    for (int i = 0; i < 4; i++) { float dv = v[i] - mu; sq += dv * dv; }
#pragma unroll
    for (int o = 16; o > 0; o >>= 1) sq += __shfl_xor_sync(0xffffffffu, sq, o);
    __syncthreads();
    if ((tid & 31) == 0) red[tid >> 5] = sq;
    __syncthreads();
    float var = (red[0] + red[1] + red[2] + red[3] + red[4] + red[5] + red[6] + red[7]) * (1.f / DDIM);
    float inv = rsqrtf(var + LN_EPS);

#pragma unroll
    for (int i = 0; i < 4; i++) {
        int d = tid + 256 * i;
        out[(size_t)token * DDIM + d] = (v[i] - mu) * inv * gamma[d] + beta[d];
    }
}

// ============================ launch ============================
extern "C" void kernel_launch(void* const* d_in, const int* in_sizes, int n_in,
                              void* d_out, int out_size) {
    const float* tgt   = (const float*)d_in[0];
    const float* Wr    = (const float*)d_in[1];
    const float* br    = (const float*)d_in[2];
    const float* W1    = (const float*)d_in[3];
    const float* b1    = (const float*)d_in[4];
    const float* W2    = (const float*)d_in[5];
    const float* b2    = (const float*)d_in[6];
    const float* gamma = (const float*)d_in[7];
    const float* beta  = (const float*)d_in[8];
    float* out = (float*)d_out;

    cudaFuncSetAttribute(mma_gemm_kernel,
                         cudaFuncAttributeMaxDynamicSharedMemorySize, SMEM_BYTES);

    init_counts_kernel<<<1, 32>>>();
    router_kernel<<<N_TOK / 8, 256>>>(tgt, Wr, br);

    // bf16 hi/lo splits
    {
        __nv_bfloat16 *xh, *xl, *w1h, *w1l, *w2h, *w2l;
        cudaGetSymbolAddress((void**)&xh,  g_Xhi);
        cudaGetSymbolAddress((void**)&xl,  g_Xlo);
        cudaGetSymbolAddress((void**)&w1h, g_W1hi);
        cudaGetSymbolAddress((void**)&w1l, g_W1lo);
        cudaGetSymbolAddress((void**)&w2h, g_W2hi);
        cudaGetSymbolAddress((void**)&w2l, g_W2lo);
        int nx = N_TOK * DDIM;              // 4,194,304
        int nw = NEXP * FDIM * DDIM;        // 33,554,432
        split_bf16_kernel<<<nx / 1024, 256>>>(tgt, xh, xl, nx);
        split_bf16_kernel<<<nw / 1024, 256>>>(W1, w1h, w1l, nw);
        split_bf16_kernel<<<nw / 1024, 256>>>(W2, w2h, w2l, nw);
    }

    // GEMM1: [cnt_e,1024] x W1^T -> H (bias+relu, bf16 hi/lo), tensor cores
    dim3 g1(N_TOK / BM, FDIM / BN, NEXP);   // (32, 32, 8): x=mt, y=nt, z=e
    mma_gemm_kernel<<<g1, 256, SMEM_BYTES>>>(1, FDIM, DDIM, b1);

    // GEMM2: [cnt_e,4096] x W2^T -> Y fp32
    dim3 g2(N_TOK / BM, DDIM / BN, NEXP);   // (32, 8, 8)
    mma_gemm_kernel<<<g2, 256, SMEM_BYTES>>>(0, DDIM, FDIM, b2);

    ln_kernel<<<N_TOK, 256>>>(tgt, gamma, beta, out);
}

// round 8
// speedup vs baseline: 1.8595x; 1.0054x over previous
#include <cuda_runtime.h>
#include <cuda_bf16.h>
#include <math.h>
#include <stdint.h>

#define N_TOK 4096      // B*S
#define DDIM  1024      // D
#define FDIM  4096      // F
#define NEXP  8         // E
#define LN_EPS 1e-5f

#define BM 128
#define BN 128
#define BK 32
#define ROWB 80                 // smem bytes per row: 32 bf16 + 8 pad = 80B
#define AT   (128 * ROWB)       // 10240 B per operand tile
#define BUFSZ (4 * AT)          // Ah, Al, Bh, Bl
#define SMEM_BYTES (2 * BUFSZ)  // 81920 B, double buffered

// ---- static device scratch (no runtime allocation allowed) ----
__device__ int   g_counts[NEXP];
__device__ int   g_rows[NEXP * N_TOK];          // value = token*2 + slot
__device__ float g_slotw[2 * N_TOK];            // softmax weight per slot
__device__ __nv_bfloat16 g_Xhi[N_TOK * DDIM];
__device__ __nv_bfloat16 g_Xlo[N_TOK * DDIM];
__device__ __nv_bfloat16 g_W1hi[NEXP * FDIM * DDIM];
__device__ __nv_bfloat16 g_W1lo[NEXP * FDIM * DDIM];
__device__ __nv_bfloat16 g_W2hi[NEXP * DDIM * FDIM];
__device__ __nv_bfloat16 g_W2lo[NEXP * DDIM * FDIM];
__device__ __nv_bfloat16 g_Hhi[(size_t)2 * N_TOK * FDIM];
__device__ __nv_bfloat16 g_Hlo[(size_t)2 * N_TOK * FDIM];
__device__ float g_Y[(size_t)2 * N_TOK * DDIM]; // [8192][1024] H@W2^T+b2 (unweighted)

// ============================ PTX helpers ============================
static __device__ __forceinline__ void cp16(uint32_t s, const void* g) {
    asm volatile("cp.async.cg.shared.global [%0], [%1], 16;" :: "r"(s), "l"(g));
}

#define LDSM4(r0, r1, r2, r3, addr)                                           \
    asm volatile("ldmatrix.sync.aligned.m8n8.x4.shared.b16 {%0,%1,%2,%3}, [%4];" \
                 : "=r"(r0), "=r"(r1), "=r"(r2), "=r"(r3) : "r"(addr))

#define MMA16816(d, a, b0, b1)                                                \
    asm volatile("mma.sync.aligned.m16n8k16.row.col.f32.bf16.bf16.f32 "       \
                 "{%0,%1,%2,%3}, {%4,%5,%6,%7}, {%8,%9}, {%0,%1,%2,%3};"      \
                 : "+f"((d)[0]), "+f"((d)[1]), "+f"((d)[2]), "+f"((d)[3])     \
                 : "r"((a)[0]), "r"((a)[1]), "r"((a)[2]), "r"((a)[3]),        \
                   "r"(b0), "r"(b1))

// ============================ small kernels ============================
__global__ void init_counts_kernel() {
    if (threadIdx.x < NEXP) g_counts[threadIdx.x] = 0;
}

// fp32 -> bf16 hi/lo split
__global__ void split_bf16_kernel(const float* __restrict__ src,
                                  __nv_bfloat16* __restrict__ hi,
                                  __nv_bfloat16* __restrict__ lo, int n) {
    int i = (blockIdx.x * blockDim.x + threadIdx.x) * 4;
    if (i >= n) return;
    float4 v = *(const float4*)(src + i);
    float vv[4] = {v.x, v.y, v.z, v.w};
    __nv_bfloat16 h[4], l[4];
#pragma unroll
    for (int j = 0; j < 4; j++) {
        h[j] = __float2bfloat16(vv[j]);
        l[j] = __float2bfloat16(vv[j] - __bfloat162float(h[j]));
    }
    __nv_bfloat162 h0; h0.x = h[0]; h0.y = h[1];
    __nv_bfloat162 h1; h1.x = h[2]; h1.y = h[3];
    __nv_bfloat162 l0; l0.x = l[0]; l0.y = l[1];
    __nv_bfloat162 l1; l1.x = l[2]; l1.y = l[3];
    *(__nv_bfloat162*)(hi + i)     = h0;
    *(__nv_bfloat162*)(hi + i + 2) = h1;
    *(__nv_bfloat162*)(lo + i)     = l0;
    *(__nv_bfloat162*)(lo + i + 2) = l1;
}

// One warp per token: 8 logits, top-2, softmax, append to expert lists.
__global__ void router_kernel(const float* __restrict__ tgt,
                              const float* __restrict__ Wr,
                              const float* __restrict__ br) {
    int token = blockIdx.x * 8 + (threadIdx.x >> 5);
    int lane  = threadIdx.x & 31;
    if (token >= N_TOK) return;

    const float* x = tgt + (size_t)token * DDIM;
    float xr[32];
#pragma unroll
    for (int i = 0; i < 32; i++) xr[i] = x[lane + 32 * i];

    float logits[NEXP];
#pragma unroll
    for (int e = 0; e < NEXP; e++) {
        const float* w = Wr + e * DDIM;
        float s = 0.f;
#pragma unroll
        for (int i = 0; i < 32; i++) s += xr[i] * w[lane + 32 * i];
#pragma unroll
        for (int o = 16; o > 0; o >>= 1) s += __shfl_xor_sync(0xffffffffu, s, o);
        logits[e] = s + br[e];
    }

    if (lane == 0) {
        int i0 = 0; float v0 = logits[0];
#pragma unroll
        for (int e = 1; e < NEXP; e++) if (logits[e] > v0) { v0 = logits[e]; i0 = e; }
        int i1 = -1; float v1 = -INFINITY;
#pragma unroll
        for (int e = 0; e < NEXP; e++) if (e != i0 && logits[e] > v1) { v1 = logits[e]; i1 = e; }
        float e1  = expf(v1 - v0);
        float inv = 1.f / (1.f + e1);
        g_slotw[2 * token]     = inv;
        g_slotw[2 * token + 1] = e1 * inv;
        int p0 = atomicAdd(&g_counts[i0], 1); g_rows[i0 * N_TOK + p0] = 2 * token;
        int p1 = atomicAdd(&g_counts[i1], 1); g_rows[i1 * N_TOK + p1] = 2 * token + 1;
    }
}

// ============================ mma.sync grouped GEMM ============================
// C[m][n] = sum_k A[m][k]*B[n][k], A/B each split bf16 hi+lo:
//   D += Ah*Bh + Ah*Bl + Al*Bh  (fp32 register accumulate)
// 256 thr = 8 warps (2 M x 4 N), warp tile 64x32, block tile 128x128, BK=32.
// Fragments hoisted: per k16-step only 12 LDSM4 (Ah x4, Bh x2, Bl x2, Al x4).
__global__ void __launch_bounds__(256, 2)
mma_gemm_kernel(int is_gemm1, int Ndim, int Kdim, const float* __restrict__ bias) {
    extern __shared__ __align__(128) char smem[];
    uint32_t sb = (uint32_t)__cvta_generic_to_shared(smem);

    int e  = blockIdx.z;
    int nt = blockIdx.y;
    int mt = blockIdx.x;     // mt varies fastest -> consecutive blocks share weight tile (L2)
    int cnt = g_counts[e];
    if (mt * BM >= cnt) return;

    const int* erows = g_rows + e * N_TOK;
    const __nv_bfloat16 *Ahb, *Alb, *Whb, *Wlb;
    if (is_gemm1) { Ahb = g_Xhi; Alb = g_Xlo; Whb = g_W1hi; Wlb = g_W1lo; }
    else          { Ahb = g_Hhi; Alb = g_Hlo; Whb = g_W2hi; Wlb = g_W2lo; }

    int tid = threadIdx.x;

    // ---- global->smem load geometry: thread -> (row = tid>>1, 32B half = tid&1) ----
    int lrow = tid >> 1;
    int kb = (tid & 1) * 16;                 // element offset of this thread's 32B
    int mr_l = mt * BM + lrow; if (mr_l > cnt - 1) mr_l = cnt - 1;
    int arow = erows[mr_l]; if (is_gemm1) arow >>= 1;
    const __nv_bfloat16* aph = Ahb + (size_t)arow * Kdim + kb;
    const __nv_bfloat16* apl = Alb + (size_t)arow * Kdim + kb;
    size_t wo = ((size_t)e * Ndim + nt * BN + lrow) * Kdim + kb;
    const __nv_bfloat16* bph = Whb + wo;
    const __nv_bfloat16* bpl = Wlb + wo;
    uint32_t dst = (uint32_t)lrow * ROWB + (tid & 1) * 32;

    // ---- fragment (ldmatrix) geometry ----
    int lane = tid & 31, wid = tid >> 5;
    int wm = wid & 1, wn = wid >> 1;         // warp tile origin (wm*64, wn*32)
    uint32_t afa = (uint32_t)(wm * 64 + (lane & 15)) * ROWB + (lane >> 4) * 16;
    uint32_t bfa = (uint32_t)(wn * 32 + (lane & 15)) * ROWB + (lane >> 4) * 16;

    float acc[4][4][4];
#pragma unroll
    for (int mi = 0; mi < 4; mi++)
#pragma unroll
        for (int ni = 0; ni < 4; ni++)
#pragma unroll
            for (int r = 0; r < 4; r++) acc[mi][ni][r] = 0.f;

    auto issue = [&](int i, int b) {
        uint32_t d = sb + (uint32_t)b * BUFSZ + dst;
        size_t ko = (size_t)i * BK;
        cp16(d,               aph + ko); cp16(d + 16,          aph + ko + 8);
        cp16(d + AT,          apl + ko); cp16(d + AT + 16,     apl + ko + 8);
        cp16(d + 2 * AT,      bph + ko); cp16(d + 2 * AT + 16, bph + ko + 8);
        cp16(d + 3 * AT,      bpl + ko); cp16(d + 3 * AT + 16, bpl + ko + 8);
        asm volatile("cp.async.commit_group;" ::: "memory");
    };

    int nch = Kdim / BK;
    issue(0, 0);
    for (int i = 0; i < nch; i++) {
        if (i + 1 < nch) {
            issue(i + 1, (i + 1) & 1);
            asm volatile("cp.async.wait_group 1;" ::: "memory");
        } else {
            asm volatile("cp.async.wait_group 0;" ::: "memory");
        }
        __syncthreads();

        uint32_t bb = sb + (uint32_t)(i & 1) * BUFSZ;
#pragma unroll
        for (int s = 0; s < 2; s++) {       // two k16 steps per chunk
            uint32_t aA = bb + afa + s * 32;          // Ah (then reused for Al)
            uint32_t aB = bb + 2 * AT + bfa + s * 32; // Bh
            uint32_t af[4][4], bhf[2][4], blf[2][4];

            // Ah fragments (4) + Bh fragments (2)
#pragma unroll
            for (int mi = 0; mi < 4; mi++)
                LDSM4(af[mi][0], af[mi][1], af[mi][2], af[mi][3], aA + mi * 16 * ROWB);
#pragma unroll
            for (int nj = 0; nj < 2; nj++)
                LDSM4(bhf[nj][0], bhf[nj][1], bhf[nj][2], bhf[nj][3], aB + nj * 16 * ROWB);

            // p0: Ah * Bh
#pragma unroll
            for (int mi = 0; mi < 4; mi++)
#pragma unroll
                for (int ni = 0; ni < 4; ni++)
                    MMA16816(acc[mi][ni], af[mi],
                             bhf[ni >> 1][ni & 1], bhf[ni >> 1][(ni & 1) + 2]);

            // Bl fragments (2)
#pragma unroll
            for (int nj = 0; nj < 2; nj++)
                LDSM4(blf[nj][0], blf[nj][1], blf[nj][2], blf[nj][3],
                      aB + AT + nj * 16 * ROWB);

            // p1: Ah * Bl
#pragma unroll
            for (int mi = 0; mi < 4; mi++)
#pragma unroll
                for (int ni = 0; ni < 4; ni++)
                    MMA16816(acc[mi][ni], af[mi],
                             blf[ni >> 1][ni & 1], blf[ni >> 1][(ni & 1) + 2]);

            // Al fragments overwrite Ah slots (4)
#pragma unroll
            for (int mi = 0; mi < 4; mi++)
                LDSM4(af[mi][0], af[mi][1], af[mi][2], af[mi][3],
                      aA + AT + mi * 16 * ROWB);

            // p2: Al * Bh
#pragma unroll
            for (int mi = 0; mi < 4; mi++)
#pragma unroll
                for (int ni = 0; ni < 4; ni++)
                    MMA16816(acc[mi][ni], af[mi],
                             bhf[ni >> 1][ni & 1], bhf[ni >> 1][(ni & 1) + 2]);
        }
        __syncthreads();
    }

    // ---- epilogue ----
    int tg = lane >> 2, tc = (lane & 3) * 2;
    const float* bbias = bias + e * Ndim + nt * BN;
    float bias_r[8];
#pragma unroll
    for (int ni = 0; ni < 4; ni++) {
        int c = wn * 32 + ni * 8 + tc;
        bias_r[2 * ni]     = __ldg(bbias + c);
        bias_r[2 * ni + 1] = __ldg(bbias + c + 1);
    }
#pragma unroll
    for (int mi = 0; mi < 4; mi++) {
#pragma unroll
        for (int half = 0; half < 2; half++) {
            int r = wm * 64 + mi * 16 + tg + half * 8;
            int mr = mt * BM + r;
            if (mr < cnt) {
                int orow = erows[mr];
#pragma unroll
                for (int ni = 0; ni < 4; ni++) {
                    int c = wn * 32 + ni * 8 + tc;
                    float v0 = acc[mi][ni][half * 2]     + bias_r[2 * ni];
                    float v1 = acc[mi][ni][half * 2 + 1] + bias_r[2 * ni + 1];
                    int n = nt * BN + c;
                    if (is_gemm1) {
                        v0 = fmaxf(v0, 0.f); v1 = fmaxf(v1, 0.f);
                        __nv_bfloat16 h0 = __float2bfloat16(v0);
                        __nv_bfloat16 h1 = __float2bfloat16(v1);
                        __nv_bfloat162 hh; hh.x = h0; hh.y = h1;
                        __nv_bfloat162 ll;
                        ll.x = __float2bfloat16(v0 - __bfloat162float(h0));
                        ll.y = __float2bfloat16(v1 - __bfloat162float(h1));
                        *(__nv_bfloat162*)(g_Hhi + (size_t)orow * FDIM + n) = hh;
                        *(__nv_bfloat162*)(g_Hlo + (size_t)orow * FDIM + n) = ll;
                    } else {
                        float2 t; t.x = v0; t.y = v1;
                        *(float2*)(g_Y + (size_t)orow * DDIM + n) = t;
                    }
                }
            }
        }
    }
}

// ============================ LN ============================
__global__ void ln_kernel(const float* __restrict__ tgt,
                          const float* __restrict__ gamma,
                          const float* __restrict__ beta,
                          float* __restrict__ out) {
    int token = blockIdx.x;
    int tid = threadIdx.x;
    __shared__ float red[8];

    float w0 = g_slotw[2 * token], w1 = g_slotw[2 * token + 1];
    const float* x  = tgt + (size_t)token * DDIM;
    const float* y0 = g_Y + (size_t)(2 * token) * DDIM;
    const float* y1 = y0 + DDIM;

    float v[4];
    float s = 0.f;
#pragma unroll
    for (int i = 0; i < 4; i++) {
        int d = tid + 256 * i;
        v[i] = x[d] + w0 * y0[d] + w1 * y1[d];
        s += v[i];
    }
#pragma unroll
    for (int o = 16; o > 0; o >>= 1) s += __shfl_xor_sync(0xffffffffu, s, o);
    if ((tid & 31) == 0) red[tid >> 5] = s;
    __syncthreads();
    float mu = (red[0] + red[1] + red[2] + red[3] + red[4] + red[5] + red[6] + red[7]) * (1.f / DDIM);

    float sq = 0.f;
#pragma unroll
    for (int i = 0; i < 4; i++) { float dv = v[i] - mu; sq += dv * dv; }
#pragma unroll
    for (int o = 16; o > 0; o >>= 1) sq += __shfl_xor_sync(0xffffffffu, sq, o);
    __syncthreads();
    if ((tid & 31) == 0) red[tid >> 5] = sq;
    __syncthreads();
    float var = (red[0] + red[1] + red[2] + red[3] + red[4] + red[5] + red[6] + red[7]) * (1.f / DDIM);
    float inv = rsqrtf(var + LN_EPS);

#pragma unroll
    for (int i = 0; i < 4; i++) {
        int d = tid + 256 * i;
        out[(size_t)token * DDIM + d] = (v[i] - mu) * inv * gamma[d] + beta[d];
    }
}

// ============================ launch ============================
extern "C" void kernel_launch(void* const* d_in, const int* in_sizes, int n_in,
                              void* d_out, int out_size) {
    const float* tgt   = (const float*)d_in[0];
    const float* Wr    = (const float*)d_in[1];
    const float* br    = (const float*)d_in[2];
    const float* W1    = (const float*)d_in[3];
    const float* b1    = (const float*)d_in[4];
    const float* W2    = (const float*)d_in[5];
    const float* b2    = (const float*)d_in[6];
    const float* gamma = (const float*)d_in[7];
    const float* beta  = (const float*)d_in[8];
    float* out = (float*)d_out;

    cudaFuncSetAttribute(mma_gemm_kernel,
                         cudaFuncAttributeMaxDynamicSharedMemorySize, SMEM_BYTES);

    init_counts_kernel<<<1, 32>>>();
    router_kernel<<<N_TOK / 8, 256>>>(tgt, Wr, br);

    // bf16 hi/lo splits
    {
        __nv_bfloat16 *xh, *xl, *w1h, *w1l, *w2h, *w2l;
        cudaGetSymbolAddress((void**)&xh,  g_Xhi);
        cudaGetSymbolAddress((void**)&xl,  g_Xlo);
        cudaGetSymbolAddress((void**)&w1h, g_W1hi);
        cudaGetSymbolAddress((void**)&w1l, g_W1lo);
        cudaGetSymbolAddress((void**)&w2h, g_W2hi);
        cudaGetSymbolAddress((void**)&w2l, g_W2lo);
        int nx = N_TOK * DDIM;              // 4,194,304
        int nw = NEXP * FDIM * DDIM;        // 33,554,432
        split_bf16_kernel<<<nx / 1024, 256>>>(tgt, xh, xl, nx);
        split_bf16_kernel<<<nw / 1024, 256>>>(W1, w1h, w1l, nw);
        split_bf16_kernel<<<nw / 1024, 256>>>(W2, w2h, w2l, nw);
    }

    // GEMM1: [cnt_e,1024] x W1^T -> H (bias+relu, bf16 hi/lo), tensor cores
    dim3 g1(N_TOK / BM, FDIM / BN, NEXP);   // (32, 32, 8): x=mt, y=nt, z=e
    mma_gemm_kernel<<<g1, 256, SMEM_BYTES>>>(1, FDIM, DDIM, b1);

    // GEMM2: [cnt_e,4096] x W2^T -> Y fp32
    dim3 g2(N_TOK / BM, DDIM / BN, NEXP);   // (32, 8, 8)
    mma_gemm_kernel<<<g2, 256, SMEM_BYTES>>>(0, DDIM, FDIM, b2);

    ln_kernel<<<N_TOK, 256>>>(tgt, gamma, beta, out);
}